// round 11
// baseline (speedup 1.0000x reference)
#include <cuda_runtime.h>
#include <cstdint>

#define BB 2
#define CC 64
#define HH 384
#define WW 384
#define OMD 112
#define OMU 108
#define HWSZ (HH*WW)
#define NPIX (BB*HH*WW)
#define NBLK (BB*HH*6)

typedef unsigned long long u64;

__device__ __forceinline__ u64 pack2(float lo, float hi) {
    u64 r; asm("mov.b64 %0,{%1,%2};" : "=l"(r) : "f"(lo), "f"(hi)); return r;
}
__device__ __forceinline__ u64 bcast2(float v) { return pack2(v, v); }
__device__ __forceinline__ void fma2(u64& d, u64 a, u64 b, u64 c) {
    asm("fma.rn.f32x2 %0,%1,%2,%3;" : "=l"(d) : "l"(a), "l"(b), "l"(c));
}
__device__ __forceinline__ float2 unpk(u64 v) {
    float2 r; asm("mov.b64 {%0,%1},%2;" : "=f"(r.x), "=f"(r.y) : "l"(v)); return r;
}

// Scratch
__device__ __align__(16) float g_value[(size_t)NPIX*CC];   // NHWC fp32
__device__ float g_ovf[(size_t)NBLK*256*27];               // slow-path om spill

extern __shared__ float dyn_smem[];

// ---------------------------------------------------------------------------
// Kernel 1: value = x @ Wv + bv  (NCHW in -> NHWC out), fp32.
// 128 px x 64 co per block, 4px x 8co tiles, f32x2.
// ---------------------------------------------------------------------------
__global__ void __launch_bounds__(256) k_value(const float* __restrict__ inp,
                                               const float* __restrict__ Wv,
                                               const float* __restrict__ bv) {
    float* As = dyn_smem;            // 64*132
    float* Bs = As + 64 * 132;       // 64*68
    int t   = threadIdx.x;
    int px0 = blockIdx.x * 128;
    int b   = px0 / HWSZ;
    int hw0 = px0 % HWSZ;

    const float* ib = inp + (size_t)b * CC * HWSZ + hw0;
    for (int idx = t; idx < 2048; idx += 256) {
        int c = idx >> 5, q = idx & 31;
        *reinterpret_cast<float4*>(&As[c * 132 + q * 4]) =
            *reinterpret_cast<const float4*>(ib + (size_t)c * HWSZ + q * 4);
    }
    for (int idx = t; idx < 1024; idx += 256) {
        int c = idx >> 4, q = idx & 15;
        *reinterpret_cast<float4*>(&Bs[c * 68 + q * 4]) =
            *reinterpret_cast<const float4*>(Wv + c * 64 + q * 4);
    }
    __syncthreads();

    int tc = t & 7, tp = t >> 3;
    u64 acc[2][8];
    {
        float4 b0 = *reinterpret_cast<const float4*>(bv + tc * 4);
        float4 b1 = *reinterpret_cast<const float4*>(bv + 32 + tc * 4);
        u64 bb[8] = {bcast2(b0.x), bcast2(b0.y), bcast2(b0.z), bcast2(b0.w),
                     bcast2(b1.x), bcast2(b1.y), bcast2(b1.z), bcast2(b1.w)};
#pragma unroll
        for (int pp = 0; pp < 2; pp++)
#pragma unroll
            for (int j = 0; j < 8; j++) acc[pp][j] = bb[j];
    }
#pragma unroll
    for (int k = 0; k < 64; k++) {
        float4 a4 = *reinterpret_cast<float4*>(&As[k * 132 + tp * 4]);
        u64 ap[2] = {pack2(a4.x, a4.y), pack2(a4.z, a4.w)};
        float4 w0 = *reinterpret_cast<float4*>(&Bs[k * 68 + tc * 4]);
        float4 w1 = *reinterpret_cast<float4*>(&Bs[k * 68 + 32 + tc * 4]);
        u64 wb[8] = {bcast2(w0.x), bcast2(w0.y), bcast2(w0.z), bcast2(w0.w),
                     bcast2(w1.x), bcast2(w1.y), bcast2(w1.z), bcast2(w1.w)};
#pragma unroll
        for (int pp = 0; pp < 2; pp++)
#pragma unroll
            for (int j = 0; j < 8; j++)
                fma2(acc[pp][j], ap[pp], wb[j], acc[pp][j]);
    }

    float* vb = g_value + (size_t)px0 * 64;
#pragma unroll
    for (int pp = 0; pp < 2; pp++) {
        float2 u[8];
#pragma unroll
        for (int j = 0; j < 8; j++) u[j] = unpk(acc[pp][j]);
        int pxe = tp * 4 + pp * 2;
        float4 e0 = {u[0].x, u[1].x, u[2].x, u[3].x};
        float4 e1 = {u[4].x, u[5].x, u[6].x, u[7].x};
        float4 o0 = {u[0].y, u[1].y, u[2].y, u[3].y};
        float4 o1 = {u[4].y, u[5].y, u[6].y, u[7].y};
        float* de = vb + pxe * 64;
        *reinterpret_cast<float4*>(de + tc * 4)      = e0;
        *reinterpret_cast<float4*>(de + 32 + tc * 4) = e1;
        *reinterpret_cast<float4*>(de + 64 + tc * 4) = o0;
        *reinterpret_cast<float4*>(de + 96 + tc * 4) = o1;
    }
}

// ---------------------------------------------------------------------------
// Kernel 2 (fused): depthwise 3x3 -> om GEMM -> sampling -> output GEMM
// 64 px of one row per block. 53.7KB dynamic smem -> 4 blocks/SM.
// overlay (floats): seg0 [0,6912):      itr(4352,stride68) -> om_s(6912) -> sbT(4352)
//                   seg1 [6912,13312):  dwt(4352) -> wcell(6400,stride25) -> wo_s(4352)
//                   bom_s [13312,13424)
// Sampling owned per-thread: t = (px<<2)|g gathers its own 16 channels.
// ---------------------------------------------------------------------------
__global__ void __launch_bounds__(256, 4) k_dwso(const float* __restrict__ inp,
                                                 const float* __restrict__ Wdw,
                                                 const float* __restrict__ bdw,
                                                 const float* __restrict__ Wom,
                                                 const float* __restrict__ bom,
                                                 const float* __restrict__ Wo,
                                                 float* __restrict__ out) {
    float* itr   = dyn_smem;                 // 64*68 conv rows
    float* om_s  = dyn_smem;                 // 6912
    float* sbT   = dyn_smem;                 // 4352 (B,C)
    float* dwt   = dyn_smem + 6912;          // 4352
    float* wcell = dyn_smem + 6912;          // 6400 (A,B), stride 25
    float* wo_s  = dyn_smem + 6912;          // 4352 (C)
    float* bom_s = dyn_smem + 13312;         // 112

    int blk  = blockIdx.x;
    int tile = blk % 6;
    int row  = (blk / 6) % HH;
    int b    = blk / (6 * HH);
    int x0   = tile * 64;
    int t    = threadIdx.x;
    bool interior = (row >= 2) && (row < HH - 2) && (tile >= 1) && (tile <= 4);

    if (t < 112) bom_s[t] = bom[t];

    // ---- depthwise conv: halo streamed row-by-row; contiguous 16-px span ----
    int c    = t & 63;
    int base = (t >> 6) * 16;
    float accv[16];
    {
        float bd = bdw[c];
#pragma unroll
        for (int i = 0; i < 16; i++) accv[i] = bd;
    }
    const float* ibs = inp + (size_t)b * CC * HWSZ;

    for (int r = 0; r < 3; r++) {
        int gy = row - 1 + r;
        __syncthreads();
        if (gy >= 0 && gy < HH) {
            const float* rbase = ibs + (size_t)gy * WW + x0 - 1;
            for (int i = t; i < 64 * 66; i += 256) {
                int ci = i / 66, xx = i - ci * 66;
                int gx = x0 - 1 + xx;
                float v = 0.f;
                if (gx >= 0 && gx < WW)
                    v = rbase[(size_t)ci * HWSZ + xx];
                itr[ci * 68 + xx] = v;
            }
        } else {
            for (int i = t; i < 64 * 66; i += 256) {
                int ci = i / 66, xx = i - ci * 66;
                itr[ci * 68 + xx] = 0.f;
            }
        }
        __syncthreads();
        float w0 = __ldg(Wdw + c * 9 + r * 3);
        float w1 = __ldg(Wdw + c * 9 + r * 3 + 1);
        float w2 = __ldg(Wdw + c * 9 + r * 3 + 2);
        const float* itc = itr + c * 68 + base;
        float4 xa = *reinterpret_cast<const float4*>(itc);
        float4 xb = *reinterpret_cast<const float4*>(itc + 4);
        float4 xc = *reinterpret_cast<const float4*>(itc + 8);
        float4 xd = *reinterpret_cast<const float4*>(itc + 12);
        float4 xe = *reinterpret_cast<const float4*>(itc + 16);
        float q[20] = {xa.x, xa.y, xa.z, xa.w, xb.x, xb.y, xb.z, xb.w,
                       xc.x, xc.y, xc.z, xc.w, xd.x, xd.y, xd.z, xd.w,
                       xe.x, xe.y, xe.z, xe.w};
#pragma unroll
        for (int i = 0; i < 16; i++)
            accv[i] += q[i] * w0 + q[i + 1] * w1 + q[i + 2] * w2;
    }
    __syncthreads();                   // conv itr reads complete
#pragma unroll
    for (int i = 0; i < 4; i++) {
        float4 o = {accv[4 * i], accv[4 * i + 1], accv[4 * i + 2], accv[4 * i + 3]};
        *reinterpret_cast<float4*>(&dwt[c * 68 + base + 4 * i]) = o;
    }
    __syncthreads();                   // dwt visible

    // ---- om GEMM -> om_s; Wom via __ldg ----
    {
        int jq = t & 31, tp = t >> 5;
        if (jq < 27) {
            u64 acc[4][4];
#pragma unroll
            for (int j = 0; j < 4; j++) {
                u64 bb = bcast2(bom_s[jq * 4 + j]);
#pragma unroll
                for (int pp = 0; pp < 4; pp++) acc[pp][j] = bb;
            }
#pragma unroll
            for (int k = 0; k < 64; k++) {
                float4 a0 = *reinterpret_cast<float4*>(&dwt[k * 68 + tp * 8]);
                float4 a1 = *reinterpret_cast<float4*>(&dwt[k * 68 + tp * 8 + 4]);
                u64 ap[4] = {pack2(a0.x, a0.y), pack2(a0.z, a0.w),
                             pack2(a1.x, a1.y), pack2(a1.z, a1.w)};
                float4 w4 = __ldg(reinterpret_cast<const float4*>(Wom + k * OMD + jq * 4));
                u64 wb[4] = {bcast2(w4.x), bcast2(w4.y), bcast2(w4.z), bcast2(w4.w)};
#pragma unroll
                for (int pp = 0; pp < 4; pp++)
#pragma unroll
                    for (int j = 0; j < 4; j++)
                        fma2(acc[pp][j], ap[pp], wb[j], acc[pp][j]);
            }
#pragma unroll
            for (int pp = 0; pp < 4; pp++) {
                float2 u0 = unpk(acc[pp][0]), u1 = unpk(acc[pp][1]);
                float2 u2 = unpk(acc[pp][2]), u3 = unpk(acc[pp][3]);
                float4 oe = {u0.x, u1.x, u2.x, u3.x};
                float4 oo = {u0.y, u1.y, u2.y, u3.y};
                int px = tp * 8 + pp * 2;
                *reinterpret_cast<float4*>(om_s + px * OMU + jq * 4)       = oe;
                *reinterpret_cast<float4*>(om_s + (px + 1) * OMU + jq * 4) = oo;
            }
        }
    }
    __syncthreads();                   // om_s done; dwt dead

    // ---- Phase A: thread (px,g) builds its 5x5 cell weights in wcell ----
    int ovf;
    {
        int px = t >> 2, g = t & 3;
        const float* omp = om_s + px * 108 + g * 27;
        float* wc = wcell + t * 25;
#pragma unroll
        for (int i = 0; i < 25; i++) wc[i] = 0.f;
        ovf = 0;
#pragma unroll
        for (int k = 0; k < 9; k++) {
            float dx = omp[2 * k];
            float dy = omp[2 * k + 1];
            float m  = omp[18 + k];
            float fx = (float)(k % 3 - 1) + dx;
            float fy = (float)(k / 3 - 1) + dy;
            float fxf = floorf(fx), fyf = floorf(fy);
            int rx = (int)fxf + 2, ry = (int)fyf + 2;
            if ((unsigned)rx <= 3u && (unsigned)ry <= 3u) {
                float wx1 = fx - fxf, wy1 = fy - fyf;
                float wx0 = 1.f - wx1;
                float wa = m * (1.f - wy1), wb = m * wy1;
                int bix = ry * 5 + rx;
                wc[bix]     += wa * wx0;
                wc[bix + 1] += wa * wx1;
                wc[bix + 5] += wb * wx0;
                wc[bix + 6] += wb * wx1;
            } else ovf = 1;
        }
        if (ovf) {                     // essentially never on this data
            float* dst = g_ovf + ((size_t)blk * 256 + t) * 27;
            for (int i = 0; i < 27; i++) dst[i] = omp[i];
        }
    }
    __syncthreads();                   // om_s dead; sbT may overwrite

    // ---- Phase B: thread (px,g) gathers its 16 channels over 25 cells ----
    {
        int px = t >> 2, g = t & 3;
        int xg = x0 + px;
        const float* wc = wcell + t * 25;
        const float* vb = g_value + (size_t)b * HWSZ * 64;
        float acc[16];
#pragma unroll
        for (int i = 0; i < 16; i++) acc[i] = 0.f;

        if (interior) {
            const float* p0 = vb + ((row - 2) * WW + (xg - 2)) * 64 + g * 16;
#pragma unroll
            for (int ry = 0; ry < 5; ry++) {
                const float* rp = p0 + ry * (WW * 64);
#pragma unroll
                for (int rx = 0; rx < 5; rx++) {
                    float w = wc[ry * 5 + rx];
                    const float4* cp = reinterpret_cast<const float4*>(rp + rx * 64);
                    float4 v0 = cp[0], v1 = cp[1], v2 = cp[2], v3 = cp[3];
                    acc[0]  += w * v0.x; acc[1]  += w * v0.y;
                    acc[2]  += w * v0.z; acc[3]  += w * v0.w;
                    acc[4]  += w * v1.x; acc[5]  += w * v1.y;
                    acc[6]  += w * v1.z; acc[7]  += w * v1.w;
                    acc[8]  += w * v2.x; acc[9]  += w * v2.y;
                    acc[10] += w * v2.z; acc[11] += w * v2.w;
                    acc[12] += w * v3.x; acc[13] += w * v3.y;
                    acc[14] += w * v3.z; acc[15] += w * v3.w;
                }
            }
        } else {
#pragma unroll
            for (int ry = 0; ry < 5; ry++) {
                int yy = row + ry - 2;
                if (yy < 0 || yy >= HH) continue;
                const float* rp = vb + ((size_t)yy * WW) * 64 + g * 16;
#pragma unroll
                for (int rx = 0; rx < 5; rx++) {
                    int xx = xg + rx - 2;
                    if (xx < 0 || xx >= WW) continue;
                    float w = wc[ry * 5 + rx];
                    const float4* cp = reinterpret_cast<const float4*>(rp + xx * 64);
                    float4 v0 = cp[0], v1 = cp[1], v2 = cp[2], v3 = cp[3];
                    acc[0]  += w * v0.x; acc[1]  += w * v0.y;
                    acc[2]  += w * v0.z; acc[3]  += w * v0.w;
                    acc[4]  += w * v1.x; acc[5]  += w * v1.y;
                    acc[6]  += w * v1.z; acc[7]  += w * v1.w;
                    acc[8]  += w * v2.x; acc[9]  += w * v2.y;
                    acc[10] += w * v2.z; acc[11] += w * v2.w;
                    acc[12] += w * v3.x; acc[13] += w * v3.y;
                    acc[14] += w * v3.z; acc[15] += w * v3.w;
                }
            }
        }

        if (ovf) {                     // rare: out-of-window points, own 16 ch
            const float* gomp = g_ovf + ((size_t)blk * 256 + t) * 27;
            for (int k = 0; k < 9; k++) {
                float dx = gomp[2 * k];
                float dy = gomp[2 * k + 1];
                float m  = gomp[18 + k];
                float fx = (float)(k % 3 - 1) + dx;
                float fy = (float)(k / 3 - 1) + dy;
                float fxf = floorf(fx), fyf = floorf(fy);
                int rx = (int)fxf + 2, ry = (int)fyf + 2;
                if ((unsigned)rx <= 3u && (unsigned)ry <= 3u) continue;
                float wx1 = fx - fxf, wy1 = fy - fyf;
                int xi = xg + (int)fxf, yi = row + (int)fyf;
                for (int dyy = 0; dyy < 2; dyy++) {
                    int yy = yi + dyy;
                    float wy = dyy ? wy1 : 1.f - wy1;
                    bool vy = (yy >= 0) && (yy < HH);
                    int yc = min(max(yy, 0), HH - 1);
                    for (int dxx = 0; dxx < 2; dxx++) {
                        int xx = xi + dxx;
                        float wx = dxx ? wx1 : 1.f - wx1;
                        bool vx = (xx >= 0) && (xx < WW);
                        int xc = min(max(xx, 0), WW - 1);
                        float wgt = (vx && vy) ? (m * wy * wx) : 0.f;
                        const float4* cp = reinterpret_cast<const float4*>(
                            vb + ((size_t)yc * WW + xc) * 64 + g * 16);
                        float4 v0 = cp[0], v1 = cp[1], v2 = cp[2], v3 = cp[3];
                        acc[0]  += wgt * v0.x; acc[1]  += wgt * v0.y;
                        acc[2]  += wgt * v0.z; acc[3]  += wgt * v0.w;
                        acc[4]  += wgt * v1.x; acc[5]  += wgt * v1.y;
                        acc[6]  += wgt * v1.z; acc[7]  += wgt * v1.w;
                        acc[8]  += wgt * v2.x; acc[9]  += wgt * v2.y;
                        acc[10] += wgt * v2.z; acc[11] += wgt * v2.w;
                        acc[12] += wgt * v3.x; acc[13] += wgt * v3.y;
                        acc[14] += wgt * v3.z; acc[15] += wgt * v3.w;
                    }
                }
            }
        }
#pragma unroll
        for (int ci = 0; ci < 16; ci++)
            sbT[(g * 16 + ci) * 68 + px] = acc[ci];
    }
    __syncthreads();                   // wcell dead; wo_s may overwrite

    // ---- stage Wo ----
    for (int idx = t; idx < 1024; idx += 256) {
        int cc = idx >> 4, q = idx & 15;
        *reinterpret_cast<float4*>(&wo_s[cc * 68 + q * 4]) =
            *reinterpret_cast<const float4*>(Wo + cc * 64 + q * 4);
    }
    __syncthreads();

    // ---- Phase C: 64px x 64co GEMM, f32x2 px-packed -> NCHW out ----
    {
        int tx = t & 15, ty = t >> 4;
        u64 acc[2][4];
#pragma unroll
        for (int pp = 0; pp < 2; pp++)
#pragma unroll
            for (int j = 0; j < 4; j++) acc[pp][j] = 0ull;
#pragma unroll
        for (int k = 0; k < 64; k++) {
            float4 a4 = *reinterpret_cast<float4*>(&sbT[k * 68 + ty * 4]);
            u64 a0 = pack2(a4.x, a4.y), a1 = pack2(a4.z, a4.w);
            float4 w4 = *reinterpret_cast<float4*>(&wo_s[k * 68 + tx * 4]);
            u64 wb[4] = {bcast2(w4.x), bcast2(w4.y), bcast2(w4.z), bcast2(w4.w)};
#pragma unroll
            for (int j = 0; j < 4; j++) {
                fma2(acc[0][j], a0, wb[j], acc[0][j]);
                fma2(acc[1][j], a1, wb[j], acc[1][j]);
            }
        }
        float* ob = out + (size_t)b * CC * HWSZ + (size_t)row * WW + x0;
#pragma unroll
        for (int j = 0; j < 4; j++) {
            float2 u0 = unpk(acc[0][j]), u1 = unpk(acc[1][j]);
            float4 o = {u0.x, u0.y, u1.x, u1.y};
            int co = tx * 4 + j;
            *reinterpret_cast<float4*>(ob + (size_t)co * HWSZ + ty * 4) = o;
        }
    }
}

// ---------------------------------------------------------------------------
extern "C" void kernel_launch(void* const* d_in, const int* in_sizes, int n_in,
                              void* d_out, int out_size) {
    const float* inp = (const float*)d_in[0];
    const float* Wv  = (const float*)d_in[1];
    const float* bv  = (const float*)d_in[2];
    const float* Wdw = (const float*)d_in[3];
    const float* bdw = (const float*)d_in[4];
    const float* Wom = (const float*)d_in[5];
    const float* bom = (const float*)d_in[6];
    const float* Wo  = (const float*)d_in[7];
    float* out = (float*)d_out;

    const int VAL_SMEM  = (64 * 132 + 64 * 68) * 4;
    const int DWSO_SMEM = 13424 * 4;
    cudaFuncSetAttribute(k_value, cudaFuncAttributeMaxDynamicSharedMemorySize, VAL_SMEM);
    cudaFuncSetAttribute(k_dwso,  cudaFuncAttributeMaxDynamicSharedMemorySize, DWSO_SMEM);

    k_value<<<NPIX / 128, 256, VAL_SMEM>>>  (inp, Wv, bv);
    k_dwso <<<NBLK,       256, DWSO_SMEM>>> (inp, Wdw, bdw, Wom, bom, Wo, out);
}

// round 12
// speedup vs baseline: 1.2574x; 1.2574x over previous
#include <cuda_runtime.h>
#include <cstdint>

#define BB 2
#define CC 64
#define HH 384
#define WW 384
#define OMD 112
#define OMU 108
#define HWSZ (HH*WW)
#define NPIX (BB*HH*WW)
#define NBLK (BB*HH*6)

typedef unsigned long long u64;

__device__ __forceinline__ u64 pack2(float lo, float hi) {
    u64 r; asm("mov.b64 %0,{%1,%2};" : "=l"(r) : "f"(lo), "f"(hi)); return r;
}
__device__ __forceinline__ u64 bcast2(float v) { return pack2(v, v); }
__device__ __forceinline__ void fma2(u64& d, u64 a, u64 b, u64 c) {
    asm("fma.rn.f32x2 %0,%1,%2,%3;" : "=l"(d) : "l"(a), "l"(b), "l"(c));
}
__device__ __forceinline__ float2 unpk(u64 v) {
    float2 r; asm("mov.b64 {%0,%1},%2;" : "=f"(r.x), "=f"(r.y) : "l"(v)); return r;
}

// Scratch
__device__ __align__(16) float g_value[(size_t)NPIX*CC];   // NHWC fp32
__device__ float g_ovf[(size_t)NBLK*256*27];               // slow-path om spill

extern __shared__ float dyn_smem[];

// ---------------------------------------------------------------------------
// Kernel 1: value = x @ Wv + bv  (NCHW in -> NHWC out), fp32.
// 128 px x 64 co per block, 4px x 8co tiles, f32x2.
// ---------------------------------------------------------------------------
__global__ void __launch_bounds__(256) k_value(const float* __restrict__ inp,
                                               const float* __restrict__ Wv,
                                               const float* __restrict__ bv) {
    float* As = dyn_smem;            // 64*132
    float* Bs = As + 64 * 132;       // 64*68
    int t   = threadIdx.x;
    int px0 = blockIdx.x * 128;
    int b   = px0 / HWSZ;
    int hw0 = px0 % HWSZ;

    const float* ib = inp + (size_t)b * CC * HWSZ + hw0;
    for (int idx = t; idx < 2048; idx += 256) {
        int c = idx >> 5, q = idx & 31;
        *reinterpret_cast<float4*>(&As[c * 132 + q * 4]) =
            *reinterpret_cast<const float4*>(ib + (size_t)c * HWSZ + q * 4);
    }
    for (int idx = t; idx < 1024; idx += 256) {
        int c = idx >> 4, q = idx & 15;
        *reinterpret_cast<float4*>(&Bs[c * 68 + q * 4]) =
            *reinterpret_cast<const float4*>(Wv + c * 64 + q * 4);
    }
    __syncthreads();

    int tc = t & 7, tp = t >> 3;
    u64 acc[2][8];
    {
        float4 b0 = *reinterpret_cast<const float4*>(bv + tc * 4);
        float4 b1 = *reinterpret_cast<const float4*>(bv + 32 + tc * 4);
        u64 bb[8] = {bcast2(b0.x), bcast2(b0.y), bcast2(b0.z), bcast2(b0.w),
                     bcast2(b1.x), bcast2(b1.y), bcast2(b1.z), bcast2(b1.w)};
#pragma unroll
        for (int pp = 0; pp < 2; pp++)
#pragma unroll
            for (int j = 0; j < 8; j++) acc[pp][j] = bb[j];
    }
#pragma unroll
    for (int k = 0; k < 64; k++) {
        float4 a4 = *reinterpret_cast<float4*>(&As[k * 132 + tp * 4]);
        u64 ap[2] = {pack2(a4.x, a4.y), pack2(a4.z, a4.w)};
        float4 w0 = *reinterpret_cast<float4*>(&Bs[k * 68 + tc * 4]);
        float4 w1 = *reinterpret_cast<float4*>(&Bs[k * 68 + 32 + tc * 4]);
        u64 wb[8] = {bcast2(w0.x), bcast2(w0.y), bcast2(w0.z), bcast2(w0.w),
                     bcast2(w1.x), bcast2(w1.y), bcast2(w1.z), bcast2(w1.w)};
#pragma unroll
        for (int pp = 0; pp < 2; pp++)
#pragma unroll
            for (int j = 0; j < 8; j++)
                fma2(acc[pp][j], ap[pp], wb[j], acc[pp][j]);
    }

    float* vb = g_value + (size_t)px0 * 64;
#pragma unroll
    for (int pp = 0; pp < 2; pp++) {
        float2 u[8];
#pragma unroll
        for (int j = 0; j < 8; j++) u[j] = unpk(acc[pp][j]);
        int pxe = tp * 4 + pp * 2;
        float4 e0 = {u[0].x, u[1].x, u[2].x, u[3].x};
        float4 e1 = {u[4].x, u[5].x, u[6].x, u[7].x};
        float4 o0 = {u[0].y, u[1].y, u[2].y, u[3].y};
        float4 o1 = {u[4].y, u[5].y, u[6].y, u[7].y};
        float* de = vb + pxe * 64;
        *reinterpret_cast<float4*>(de + tc * 4)      = e0;
        *reinterpret_cast<float4*>(de + 32 + tc * 4) = e1;
        *reinterpret_cast<float4*>(de + 64 + tc * 4) = o0;
        *reinterpret_cast<float4*>(de + 96 + tc * 4) = o1;
    }
}

// ---------------------------------------------------------------------------
// Kernel 2 (fused): depthwise 3x3 -> om GEMM -> sampling -> output GEMM
// 64 px of one row per block. 54.7KB dynamic smem -> 4 blocks/SM.
// overlay (floats): seg0 [0,6912):      itr(4288,stride67) -> om_s(6912) -> sbT(4352)
//                   seg1 [6912,13568):  dwt(4352) -> wcell(6656,stride26) -> wo_s(4352)
//                   bom_s [13568,13680)
// Phase B: warp = 2 adjacent pixels, lane = (px-half, channel-quad) -> each
// cell is one LDG.128/lane, warp footprint 2x256B contiguous (4 wavefronts).
// ---------------------------------------------------------------------------
template<bool CHK>
__device__ __forceinline__ void gather4(const float* __restrict__ vb,
                                        const float* __restrict__ wc,
                                        int row, int xg, int cb,
                                        float4& acc) {
#pragma unroll
    for (int ry = 0; ry < 5; ry++) {
        int yy = row + ry - 2;
        if (CHK && (yy < 0 || yy >= HH)) continue;
        const float* rp = vb + (size_t)yy * (WW * 64) + cb;
#pragma unroll
        for (int rx = 0; rx < 5; rx++) {
            int xx = xg + rx - 2;
            if (CHK && (xx < 0 || xx >= WW)) continue;
            float w = wc[ry * 5 + rx];
            float4 v = *reinterpret_cast<const float4*>(rp + xx * 64);
            acc.x += w * v.x; acc.y += w * v.y;
            acc.z += w * v.z; acc.w += w * v.w;
        }
    }
}

__global__ void __launch_bounds__(256, 4) k_dwso(const float* __restrict__ inp,
                                                 const float* __restrict__ Wdw,
                                                 const float* __restrict__ bdw,
                                                 const float* __restrict__ Wom,
                                                 const float* __restrict__ bom,
                                                 const float* __restrict__ Wo,
                                                 float* __restrict__ out) {
    float* itr   = dyn_smem;                 // conv rows (stride 67)
    float* om_s  = dyn_smem;                 // 6912
    float* sbT   = dyn_smem;                 // 4352 (B,C)
    float* dwt   = dyn_smem + 6912;          // 4352
    float* wcell = dyn_smem + 6912;          // 6656 (A,B), stride 26
    float* wo_s  = dyn_smem + 6912;          // 4352 (C)
    float* bom_s = dyn_smem + 13568;         // 112
    __shared__ int flags_s[256];

    int blk  = blockIdx.x;
    int tile = blk % 6;
    int row  = (blk / 6) % HH;
    int b    = blk / (6 * HH);
    int x0   = tile * 64;
    int t    = threadIdx.x;
    bool interior = (row >= 2) && (row < HH - 2) && (tile >= 1) && (tile <= 4);

    if (t < 112) bom_s[t] = bom[t];

    // ---- depthwise conv: halo streamed row-by-row; strided px mapping ----
    int c  = t & 63;
    int p0 = t >> 6;                    // px = p0 + 4*i
    float accv[16];
    {
        float bd = bdw[c];
#pragma unroll
        for (int i = 0; i < 16; i++) accv[i] = bd;
    }
    const float* ibs = inp + (size_t)b * CC * HWSZ;

    for (int r = 0; r < 3; r++) {
        int gy = row - 1 + r;
        __syncthreads();
        if (gy >= 0 && gy < HH) {
            const float* rbase = ibs + (size_t)gy * WW + x0 - 1;
            for (int i = t; i < 64 * 66; i += 256) {
                int ci = i / 66, xx = i - ci * 66;
                int gx = x0 - 1 + xx;
                float v = 0.f;
                if (gx >= 0 && gx < WW)
                    v = rbase[(size_t)ci * HWSZ + xx];
                itr[ci * 67 + xx] = v;
            }
        } else {
            for (int i = t; i < 64 * 66; i += 256) {
                int ci = i / 66, xx = i - ci * 66;
                itr[ci * 67 + xx] = 0.f;
            }
        }
        __syncthreads();
        float w0 = __ldg(Wdw + c * 9 + r * 3);
        float w1 = __ldg(Wdw + c * 9 + r * 3 + 1);
        float w2 = __ldg(Wdw + c * 9 + r * 3 + 2);
        const float* itc = itr + c * 67 + p0;
#pragma unroll
        for (int i = 0; i < 16; i++) {
            const float* q = itc + i * 4;
            accv[i] += q[0] * w0 + q[1] * w1 + q[2] * w2;
        }
    }
    __syncthreads();                   // conv itr reads done
#pragma unroll
    for (int i = 0; i < 16; i++) dwt[c * 68 + p0 + i * 4] = accv[i];
    __syncthreads();                   // dwt visible

    // ---- om GEMM -> om_s; Wom via __ldg ----
    {
        int jq = t & 31, tp = t >> 5;
        if (jq < 27) {
            u64 acc[4][4];
#pragma unroll
            for (int j = 0; j < 4; j++) {
                u64 bb = bcast2(bom_s[jq * 4 + j]);
#pragma unroll
                for (int pp = 0; pp < 4; pp++) acc[pp][j] = bb;
            }
#pragma unroll
            for (int k = 0; k < 64; k++) {
                float4 a0 = *reinterpret_cast<float4*>(&dwt[k * 68 + tp * 8]);
                float4 a1 = *reinterpret_cast<float4*>(&dwt[k * 68 + tp * 8 + 4]);
                u64 ap[4] = {pack2(a0.x, a0.y), pack2(a0.z, a0.w),
                             pack2(a1.x, a1.y), pack2(a1.z, a1.w)};
                float4 w4 = __ldg(reinterpret_cast<const float4*>(Wom + k * OMD + jq * 4));
                u64 wb[4] = {bcast2(w4.x), bcast2(w4.y), bcast2(w4.z), bcast2(w4.w)};
#pragma unroll
                for (int pp = 0; pp < 4; pp++)
#pragma unroll
                    for (int j = 0; j < 4; j++)
                        fma2(acc[pp][j], ap[pp], wb[j], acc[pp][j]);
            }
#pragma unroll
            for (int pp = 0; pp < 4; pp++) {
                float2 u0 = unpk(acc[pp][0]), u1 = unpk(acc[pp][1]);
                float2 u2 = unpk(acc[pp][2]), u3 = unpk(acc[pp][3]);
                float4 oe = {u0.x, u1.x, u2.x, u3.x};
                float4 oo = {u0.y, u1.y, u2.y, u3.y};
                int px = tp * 8 + pp * 2;
                *reinterpret_cast<float4*>(om_s + px * OMU + jq * 4)       = oe;
                *reinterpret_cast<float4*>(om_s + (px + 1) * OMU + jq * 4) = oo;
            }
        }
    }
    __syncthreads();                   // om_s done; dwt dead

    // ---- Phase A: thread (px,g) builds its 5x5 cell weights ----
    {
        int px = t >> 2, g = t & 3;
        const float* omp = om_s + px * 108 + g * 27;
        float* wc = wcell + t * 26;
#pragma unroll
        for (int i = 0; i < 25; i++) wc[i] = 0.f;
        int ovf = 0;
#pragma unroll
        for (int k = 0; k < 9; k++) {
            float dx = omp[2 * k];
            float dy = omp[2 * k + 1];
            float m  = omp[18 + k];
            float fx = (float)(k % 3 - 1) + dx;
            float fy = (float)(k / 3 - 1) + dy;
            float fxf = floorf(fx), fyf = floorf(fy);
            int rx = (int)fxf + 2, ry = (int)fyf + 2;
            if ((unsigned)rx <= 3u && (unsigned)ry <= 3u) {
                float wx1 = fx - fxf, wy1 = fy - fyf;
                float wx0 = 1.f - wx1;
                float wa = m * (1.f - wy1), wb = m * wy1;
                int bix = ry * 5 + rx;
                wc[bix]     += wa * wx0;
                wc[bix + 1] += wa * wx1;
                wc[bix + 5] += wb * wx0;
                wc[bix + 6] += wb * wx1;
            } else ovf = 1;
        }
        flags_s[t] = ovf;
        if (ovf) {                     // essentially never on this data
            float* dst = g_ovf + ((size_t)blk * 256 + t) * 27;
            for (int i = 0; i < 27; i++) dst[i] = omp[i];
        }
    }
    __syncthreads();                   // om_s dead; sbT may overwrite

    // ---- Phase B: warp = 2 px, lane = (px-half, ch-quad); LDG.128/lane ----
    {
        int lane = t & 31, wrp = t >> 5;
        int ph  = lane >> 4;           // pixel half
        int l16 = lane & 15;           // channel quad index 0..15
        int g   = l16 >> 2;            // group
        int cb  = l16 * 4;             // channel base
        const float* vb = g_value + (size_t)b * HWSZ * 64;

        for (int i = 0; i < 4; i++) {
            int p  = wrp * 8 + i * 2 + ph;   // 0..63
            int xg = x0 + p;
            const float* wc = wcell + (p * 4 + g) * 26;
            float4 acc = {0.f, 0.f, 0.f, 0.f};
            if (interior) gather4<false>(vb, wc, row, xg, cb, acc);
            else          gather4<true >(vb, wc, row, xg, cb, acc);

            if (flags_s[p * 4 + g]) {  // rare: out-of-window points
                const float* gomp = g_ovf + ((size_t)blk * 256 + p * 4 + g) * 27;
                for (int k = 0; k < 9; k++) {
                    float dx = gomp[2 * k];
                    float dy = gomp[2 * k + 1];
                    float m  = gomp[18 + k];
                    float fx = (float)(k % 3 - 1) + dx;
                    float fy = (float)(k / 3 - 1) + dy;
                    float fxf = floorf(fx), fyf = floorf(fy);
                    int rx = (int)fxf + 2, ry = (int)fyf + 2;
                    if ((unsigned)rx <= 3u && (unsigned)ry <= 3u) continue;
                    float wx1 = fx - fxf, wy1 = fy - fyf;
                    int xi = xg + (int)fxf, yi = row + (int)fyf;
                    for (int dyy = 0; dyy < 2; dyy++) {
                        int yy = yi + dyy;
                        float wy = dyy ? wy1 : 1.f - wy1;
                        bool vy = (yy >= 0) && (yy < HH);
                        int yc = min(max(yy, 0), HH - 1);
                        for (int dxx = 0; dxx < 2; dxx++) {
                            int xx = xi + dxx;
                            float wx = dxx ? wx1 : 1.f - wx1;
                            bool vx = (xx >= 0) && (xx < WW);
                            int xc = min(max(xx, 0), WW - 1);
                            float wgt = (vx && vy) ? (m * wy * wx) : 0.f;
                            float4 v = *reinterpret_cast<const float4*>(
                                vb + ((size_t)yc * WW + xc) * 64 + cb);
                            acc.x += wgt * v.x; acc.y += wgt * v.y;
                            acc.z += wgt * v.z; acc.w += wgt * v.w;
                        }
                    }
                }
            }
            sbT[(cb + 0) * 68 + p] = acc.x;
            sbT[(cb + 1) * 68 + p] = acc.y;
            sbT[(cb + 2) * 68 + p] = acc.z;
            sbT[(cb + 3) * 68 + p] = acc.w;
        }
    }
    __syncthreads();                   // wcell dead; wo_s may overwrite

    // ---- stage Wo ----
    for (int idx = t; idx < 1024; idx += 256) {
        int cc = idx >> 4, q = idx & 15;
        *reinterpret_cast<float4*>(&wo_s[cc * 68 + q * 4]) =
            *reinterpret_cast<const float4*>(Wo + cc * 64 + q * 4);
    }
    __syncthreads();

    // ---- Phase C: 64px x 64co GEMM, f32x2 px-packed -> NCHW out ----
    {
        int tx = t & 15, ty = t >> 4;
        u64 acc[2][4];
#pragma unroll
        for (int pp = 0; pp < 2; pp++)
#pragma unroll
            for (int j = 0; j < 4; j++) acc[pp][j] = 0ull;
#pragma unroll
        for (int k = 0; k < 64; k++) {
            float4 a4 = *reinterpret_cast<float4*>(&sbT[k * 68 + ty * 4]);
            u64 a0 = pack2(a4.x, a4.y), a1 = pack2(a4.z, a4.w);
            float4 w4 = *reinterpret_cast<float4*>(&wo_s[k * 68 + tx * 4]);
            u64 wb[4] = {bcast2(w4.x), bcast2(w4.y), bcast2(w4.z), bcast2(w4.w)};
#pragma unroll
            for (int j = 0; j < 4; j++) {
                fma2(acc[0][j], a0, wb[j], acc[0][j]);
                fma2(acc[1][j], a1, wb[j], acc[1][j]);
            }
        }
        float* ob = out + (size_t)b * CC * HWSZ + (size_t)row * WW + x0;
#pragma unroll
        for (int j = 0; j < 4; j++) {
            float2 u0 = unpk(acc[0][j]), u1 = unpk(acc[1][j]);
            float4 o = {u0.x, u0.y, u1.x, u1.y};
            int co = tx * 4 + j;
            *reinterpret_cast<float4*>(ob + (size_t)co * HWSZ + ty * 4) = o;
        }
    }
}

// ---------------------------------------------------------------------------
extern "C" void kernel_launch(void* const* d_in, const int* in_sizes, int n_in,
                              void* d_out, int out_size) {
    const float* inp = (const float*)d_in[0];
    const float* Wv  = (const float*)d_in[1];
    const float* bv  = (const float*)d_in[2];
    const float* Wdw = (const float*)d_in[3];
    const float* bdw = (const float*)d_in[4];
    const float* Wom = (const float*)d_in[5];
    const float* bom = (const float*)d_in[6];
    const float* Wo  = (const float*)d_in[7];
    float* out = (float*)d_out;

    const int VAL_SMEM  = (64 * 132 + 64 * 68) * 4;
    const int DWSO_SMEM = 13680 * 4;
    cudaFuncSetAttribute(k_value, cudaFuncAttributeMaxDynamicSharedMemorySize, VAL_SMEM);
    cudaFuncSetAttribute(k_dwso,  cudaFuncAttributeMaxDynamicSharedMemorySize, DWSO_SMEM);

    k_value<<<NPIX / 128, 256, VAL_SMEM>>>  (inp, Wv, bv);
    k_dwso <<<NBLK,       256, DWSO_SMEM>>> (inp, Wdw, bdw, Wom, bom, Wo, out);
}

// round 13
// speedup vs baseline: 1.4159x; 1.1261x over previous
#include <cuda_runtime.h>
#include <cuda_fp16.h>
#include <cstdint>

#define BB 2
#define CC 64
#define HH 384
#define WW 384
#define OMD 112
#define OMU 108
#define HWSZ (HH*WW)
#define NPIX (BB*HH*WW)
#define NBLK (BB*HH*6)

typedef unsigned long long u64;

__device__ __forceinline__ u64 pack2(float lo, float hi) {
    u64 r; asm("mov.b64 %0,{%1,%2};" : "=l"(r) : "f"(lo), "f"(hi)); return r;
}
__device__ __forceinline__ u64 bcast2(float v) { return pack2(v, v); }
__device__ __forceinline__ void fma2(u64& d, u64 a, u64 b, u64 c) {
    asm("fma.rn.f32x2 %0,%1,%2,%3;" : "=l"(d) : "l"(a), "l"(b), "l"(c));
}
__device__ __forceinline__ float2 unpk(u64 v) {
    float2 r; asm("mov.b64 {%0,%1},%2;" : "=f"(r.x), "=f"(r.y) : "l"(v)); return r;
}

// Scratch
__device__ __align__(16) __half g_value_h[(size_t)NPIX*CC];   // NHWC fp16
__device__ float g_ovf[(size_t)NBLK*256*27];                  // slow-path om spill

extern __shared__ float dyn_smem[];

// ---------------------------------------------------------------------------
// Kernel 1: value = x @ Wv + bv  (NCHW fp32 -> NHWC fp16)
// 128 px x 64 co per block, 4px x 8co tiles, f32x2 compute, half stores.
// ---------------------------------------------------------------------------
__global__ void __launch_bounds__(256) k_value(const float* __restrict__ inp,
                                               const float* __restrict__ Wv,
                                               const float* __restrict__ bv) {
    float* As = dyn_smem;            // 64*132
    float* Bs = As + 64 * 132;       // 64*68
    int t   = threadIdx.x;
    int px0 = blockIdx.x * 128;
    int b   = px0 / HWSZ;
    int hw0 = px0 % HWSZ;

    const float* ib = inp + (size_t)b * CC * HWSZ + hw0;
    for (int idx = t; idx < 2048; idx += 256) {
        int c = idx >> 5, q = idx & 31;
        *reinterpret_cast<float4*>(&As[c * 132 + q * 4]) =
            *reinterpret_cast<const float4*>(ib + (size_t)c * HWSZ + q * 4);
    }
    for (int idx = t; idx < 1024; idx += 256) {
        int c = idx >> 4, q = idx & 15;
        *reinterpret_cast<float4*>(&Bs[c * 68 + q * 4]) =
            *reinterpret_cast<const float4*>(Wv + c * 64 + q * 4);
    }
    __syncthreads();

    int tc = t & 7, tp = t >> 3;
    u64 acc[2][8];
    {
        float4 b0 = *reinterpret_cast<const float4*>(bv + tc * 4);
        float4 b1 = *reinterpret_cast<const float4*>(bv + 32 + tc * 4);
        u64 bb[8] = {bcast2(b0.x), bcast2(b0.y), bcast2(b0.z), bcast2(b0.w),
                     bcast2(b1.x), bcast2(b1.y), bcast2(b1.z), bcast2(b1.w)};
#pragma unroll
        for (int pp = 0; pp < 2; pp++)
#pragma unroll
            for (int j = 0; j < 8; j++) acc[pp][j] = bb[j];
    }
#pragma unroll
    for (int k = 0; k < 64; k++) {
        float4 a4 = *reinterpret_cast<float4*>(&As[k * 132 + tp * 4]);
        u64 ap[2] = {pack2(a4.x, a4.y), pack2(a4.z, a4.w)};
        float4 w0 = *reinterpret_cast<float4*>(&Bs[k * 68 + tc * 4]);
        float4 w1 = *reinterpret_cast<float4*>(&Bs[k * 68 + 32 + tc * 4]);
        u64 wb[8] = {bcast2(w0.x), bcast2(w0.y), bcast2(w0.z), bcast2(w0.w),
                     bcast2(w1.x), bcast2(w1.y), bcast2(w1.z), bcast2(w1.w)};
#pragma unroll
        for (int pp = 0; pp < 2; pp++)
#pragma unroll
            for (int j = 0; j < 8; j++)
                fma2(acc[pp][j], ap[pp], wb[j], acc[pp][j]);
    }

    __half* vb = g_value_h + (size_t)px0 * 64;
#pragma unroll
    for (int pp = 0; pp < 2; pp++) {
        float2 u[8];
#pragma unroll
        for (int j = 0; j < 8; j++) u[j] = unpk(acc[pp][j]);
        int pxe = tp * 4 + pp * 2;
        union { __half2 h[2]; uint2 v; } pk;
        __half* de = vb + pxe * 64;
        pk.h[0] = __floats2half2_rn(u[0].x, u[1].x);
        pk.h[1] = __floats2half2_rn(u[2].x, u[3].x);
        *reinterpret_cast<uint2*>(de + tc * 4) = pk.v;
        pk.h[0] = __floats2half2_rn(u[4].x, u[5].x);
        pk.h[1] = __floats2half2_rn(u[6].x, u[7].x);
        *reinterpret_cast<uint2*>(de + 32 + tc * 4) = pk.v;
        pk.h[0] = __floats2half2_rn(u[0].y, u[1].y);
        pk.h[1] = __floats2half2_rn(u[2].y, u[3].y);
        *reinterpret_cast<uint2*>(de + 64 + tc * 4) = pk.v;
        pk.h[0] = __floats2half2_rn(u[4].y, u[5].y);
        pk.h[1] = __floats2half2_rn(u[6].y, u[7].y);
        *reinterpret_cast<uint2*>(de + 96 + tc * 4) = pk.v;
    }
}

// ---------------------------------------------------------------------------
// Kernel 2 (fused): depthwise 3x3 -> om GEMM -> sampling -> output GEMM
// 64 px of one row per block. 54.7KB dynamic smem -> 4 blocks/SM.
// overlay (floats): seg0 [0,6912):      itr(4352,stride68) -> om_s(6912) -> sbT(4352)
//                   seg1 [6912,13568):  dwt(4352) -> wcell(6656,stride26) -> wo_s(4352)
//                   bom_s [13568,13680)
// Phase B: warp = 2 px, lane = (px-half, ch-quad); 8B half loads -> 2 wf/cell.
// ---------------------------------------------------------------------------
__device__ __forceinline__ void acc4h(const __half* p, float w, float4& acc) {
    uint2 raw = *reinterpret_cast<const uint2*>(p);
    float2 v0 = __half22float2(*reinterpret_cast<__half2*>(&raw.x));
    float2 v1 = __half22float2(*reinterpret_cast<__half2*>(&raw.y));
    acc.x += w * v0.x; acc.y += w * v0.y;
    acc.z += w * v1.x; acc.w += w * v1.y;
}

template<bool CHK>
__device__ __forceinline__ void gather4h(const __half* __restrict__ vb,
                                         const float* __restrict__ wc,
                                         int row, int xg, int cb,
                                         float4& acc) {
#pragma unroll
    for (int ry = 0; ry < 5; ry++) {
        int yy = row + ry - 2;
        if (CHK && (yy < 0 || yy >= HH)) continue;
        const __half* rp = vb + (size_t)yy * (WW * 64) + cb;
#pragma unroll
        for (int rx = 0; rx < 5; rx++) {
            int xx = xg + rx - 2;
            if (CHK && (xx < 0 || xx >= WW)) continue;
            acc4h(rp + xx * 64, wc[ry * 5 + rx], acc);
        }
    }
}

__global__ void __launch_bounds__(256, 4) k_dwso(const float* __restrict__ inp,
                                                 const float* __restrict__ Wdw,
                                                 const float* __restrict__ bdw,
                                                 const float* __restrict__ Wom,
                                                 const float* __restrict__ bom,
                                                 const float* __restrict__ Wo,
                                                 float* __restrict__ out) {
    float* itr   = dyn_smem;                 // 64*68 conv rows
    float* om_s  = dyn_smem;                 // 6912
    float* sbT   = dyn_smem;                 // 4352 (B,C)
    float* dwt   = dyn_smem + 6912;          // 4352
    float* wcell = dyn_smem + 6912;          // 6656 (A,B), stride 26
    float* wo_s  = dyn_smem + 6912;          // 4352 (C)
    float* bom_s = dyn_smem + 13568;         // 112
    __shared__ int flags_s[256];

    int blk  = blockIdx.x;
    int tile = blk % 6;
    int row  = (blk / 6) % HH;
    int b    = blk / (6 * HH);
    int x0   = tile * 64;
    int t    = threadIdx.x;
    bool interior = (row >= 2) && (row < HH - 2) && (tile >= 1) && (tile <= 4);

    if (t < 112) bom_s[t] = bom[t];

    // ---- depthwise conv: halo streamed row-by-row; contiguous 16-px span,
    //      5x LDS.128 sliding window per row (stride 68: conflict-free .128) ----
    int c    = t & 63;
    int base = (t >> 6) * 16;
    float accv[16];
    {
        float bd = bdw[c];
#pragma unroll
        for (int i = 0; i < 16; i++) accv[i] = bd;
    }
    const float* ibs = inp + (size_t)b * CC * HWSZ;

    for (int r = 0; r < 3; r++) {
        int gy = row - 1 + r;
        __syncthreads();
        if (gy >= 0 && gy < HH) {
            const float* rbase = ibs + (size_t)gy * WW + x0 - 1;
            for (int i = t; i < 64 * 66; i += 256) {
                int ci = i / 66, xx = i - ci * 66;
                int gx = x0 - 1 + xx;
                float v = 0.f;
                if (gx >= 0 && gx < WW)
                    v = rbase[(size_t)ci * HWSZ + xx];
                itr[ci * 68 + xx] = v;
            }
        } else {
            for (int i = t; i < 64 * 66; i += 256) {
                int ci = i / 66, xx = i - ci * 66;
                itr[ci * 68 + xx] = 0.f;
            }
        }
        __syncthreads();
        float w0 = __ldg(Wdw + c * 9 + r * 3);
        float w1 = __ldg(Wdw + c * 9 + r * 3 + 1);
        float w2 = __ldg(Wdw + c * 9 + r * 3 + 2);
        const float* itc = itr + c * 68 + base;
        float4 xa = *reinterpret_cast<const float4*>(itc);
        float4 xb = *reinterpret_cast<const float4*>(itc + 4);
        float4 xc = *reinterpret_cast<const float4*>(itc + 8);
        float4 xd = *reinterpret_cast<const float4*>(itc + 12);
        float4 xe = *reinterpret_cast<const float4*>(itc + 16);
        float s[20];
        s[0]=xa.x; s[1]=xa.y; s[2]=xa.z; s[3]=xa.w;
        s[4]=xb.x; s[5]=xb.y; s[6]=xb.z; s[7]=xb.w;
        s[8]=xc.x; s[9]=xc.y; s[10]=xc.z; s[11]=xc.w;
        s[12]=xd.x; s[13]=xd.y; s[14]=xd.z; s[15]=xd.w;
        s[16]=xe.x; s[17]=xe.y; s[18]=xe.z; s[19]=xe.w;
#pragma unroll
        for (int i = 0; i < 16; i++)
            accv[i] += s[i] * w0 + s[i + 1] * w1 + s[i + 2] * w2;
    }
    __syncthreads();                   // conv itr reads done
#pragma unroll
    for (int i = 0; i < 4; i++) {
        float4 o = {accv[4*i], accv[4*i+1], accv[4*i+2], accv[4*i+3]};
        *reinterpret_cast<float4*>(&dwt[c * 68 + base + 4 * i]) = o;
    }
    __syncthreads();                   // dwt visible

    // ---- om GEMM -> om_s; Wom via __ldg ----
    {
        int jq = t & 31, tp = t >> 5;
        if (jq < 27) {
            u64 acc[4][4];
#pragma unroll
            for (int j = 0; j < 4; j++) {
                u64 bb = bcast2(bom_s[jq * 4 + j]);
#pragma unroll
                for (int pp = 0; pp < 4; pp++) acc[pp][j] = bb;
            }
#pragma unroll
            for (int k = 0; k < 64; k++) {
                float4 a0 = *reinterpret_cast<float4*>(&dwt[k * 68 + tp * 8]);
                float4 a1 = *reinterpret_cast<float4*>(&dwt[k * 68 + tp * 8 + 4]);
                u64 ap[4] = {pack2(a0.x, a0.y), pack2(a0.z, a0.w),
                             pack2(a1.x, a1.y), pack2(a1.z, a1.w)};
                float4 w4 = __ldg(reinterpret_cast<const float4*>(Wom + k * OMD + jq * 4));
                u64 wb[4] = {bcast2(w4.x), bcast2(w4.y), bcast2(w4.z), bcast2(w4.w)};
#pragma unroll
                for (int pp = 0; pp < 4; pp++)
#pragma unroll
                    for (int j = 0; j < 4; j++)
                        fma2(acc[pp][j], ap[pp], wb[j], acc[pp][j]);
            }
#pragma unroll
            for (int pp = 0; pp < 4; pp++) {
                float2 u0 = unpk(acc[pp][0]), u1 = unpk(acc[pp][1]);
                float2 u2 = unpk(acc[pp][2]), u3 = unpk(acc[pp][3]);
                float4 oe = {u0.x, u1.x, u2.x, u3.x};
                float4 oo = {u0.y, u1.y, u2.y, u3.y};
                int px = tp * 8 + pp * 2;
                *reinterpret_cast<float4*>(om_s + px * OMU + jq * 4)       = oe;
                *reinterpret_cast<float4*>(om_s + (px + 1) * OMU + jq * 4) = oo;
            }
        }
    }
    __syncthreads();                   // om_s done; dwt dead

    // ---- Phase A: thread (px,g) builds its 5x5 cell weights ----
    {
        int px = t >> 2, g = t & 3;
        const float* omp = om_s + px * 108 + g * 27;
        float* wc = wcell + t * 26;
#pragma unroll
        for (int i = 0; i < 25; i++) wc[i] = 0.f;
        int ovf = 0;
#pragma unroll
        for (int k = 0; k < 9; k++) {
            float dx = omp[2 * k];
            float dy = omp[2 * k + 1];
            float m  = omp[18 + k];
            float fx = (float)(k % 3 - 1) + dx;
            float fy = (float)(k / 3 - 1) + dy;
            float fxf = floorf(fx), fyf = floorf(fy);
            int rx = (int)fxf + 2, ry = (int)fyf + 2;
            if ((unsigned)rx <= 3u && (unsigned)ry <= 3u) {
                float wx1 = fx - fxf, wy1 = fy - fyf;
                float wx0 = 1.f - wx1;
                float wa = m * (1.f - wy1), wb = m * wy1;
                int bix = ry * 5 + rx;
                wc[bix]     += wa * wx0;
                wc[bix + 1] += wa * wx1;
                wc[bix + 5] += wb * wx0;
                wc[bix + 6] += wb * wx1;
            } else ovf = 1;
        }
        flags_s[t] = ovf;
        if (ovf) {                     // essentially never on this data
            float* dst = g_ovf + ((size_t)blk * 256 + t) * 27;
            for (int i = 0; i < 27; i++) dst[i] = omp[i];
        }
    }
    __syncthreads();                   // om_s dead; sbT may overwrite

    // ---- Phase B: warp = 2 px, lane = (px-half, ch-quad); 8B half loads ----
    {
        int lane = t & 31, wrp = t >> 5;
        int ph  = lane >> 4;
        int l16 = lane & 15;
        int g   = l16 >> 2;
        int cb  = l16 * 4;
        const __half* vb = g_value_h + (size_t)b * HWSZ * 64;

        for (int i = 0; i < 4; i++) {
            int p  = wrp * 8 + i * 2 + ph;
            int xg = x0 + p;
            const float* wc = wcell + (p * 4 + g) * 26;
            float4 acc = {0.f, 0.f, 0.f, 0.f};
            if (interior) gather4h<false>(vb, wc, row, xg, cb, acc);
            else          gather4h<true >(vb, wc, row, xg, cb, acc);

            if (flags_s[p * 4 + g]) {  // rare: out-of-window points
                const float* gomp = g_ovf + ((size_t)blk * 256 + p * 4 + g) * 27;
                for (int k = 0; k < 9; k++) {
                    float dx = gomp[2 * k];
                    float dy = gomp[2 * k + 1];
                    float m  = gomp[18 + k];
                    float fx = (float)(k % 3 - 1) + dx;
                    float fy = (float)(k / 3 - 1) + dy;
                    float fxf = floorf(fx), fyf = floorf(fy);
                    int rx = (int)fxf + 2, ry = (int)fyf + 2;
                    if ((unsigned)rx <= 3u && (unsigned)ry <= 3u) continue;
                    float wx1 = fx - fxf, wy1 = fy - fyf;
                    int xi = xg + (int)fxf, yi = row + (int)fyf;
                    for (int dyy = 0; dyy < 2; dyy++) {
                        int yy = yi + dyy;
                        float wy = dyy ? wy1 : 1.f - wy1;
                        bool vy = (yy >= 0) && (yy < HH);
                        int yc = min(max(yy, 0), HH - 1);
                        for (int dxx = 0; dxx < 2; dxx++) {
                            int xx = xi + dxx;
                            float wx = dxx ? wx1 : 1.f - wx1;
                            bool vx = (xx >= 0) && (xx < WW);
                            int xc = min(max(xx, 0), WW - 1);
                            float wgt = (vx && vy) ? (m * wy * wx) : 0.f;
                            acc4h(vb + ((size_t)yc * WW + xc) * 64 + cb, wgt, acc);
                        }
                    }
                }
            }
            sbT[(cb + 0) * 68 + p] = acc.x;
            sbT[(cb + 1) * 68 + p] = acc.y;
            sbT[(cb + 2) * 68 + p] = acc.z;
            sbT[(cb + 3) * 68 + p] = acc.w;
        }
    }
    __syncthreads();                   // wcell dead; wo_s may overwrite

    // ---- stage Wo ----
    for (int idx = t; idx < 1024; idx += 256) {
        int cc = idx >> 4, q = idx & 15;
        *reinterpret_cast<float4*>(&wo_s[cc * 68 + q * 4]) =
            *reinterpret_cast<const float4*>(Wo + cc * 64 + q * 4);
    }
    __syncthreads();

    // ---- Phase C: 64px x 64co GEMM, f32x2 px-packed -> NCHW out ----
    {
        int tx = t & 15, ty = t >> 4;
        u64 acc[2][4];
#pragma unroll
        for (int pp = 0; pp < 2; pp++)
#pragma unroll
            for (int j = 0; j < 4; j++) acc[pp][j] = 0ull;
#pragma unroll
        for (int k = 0; k < 64; k++) {
            float4 a4 = *reinterpret_cast<float4*>(&sbT[k * 68 + ty * 4]);
            u64 a0 = pack2(a4.x, a4.y), a1 = pack2(a4.z, a4.w);
            float4 w4 = *reinterpret_cast<float4*>(&wo_s[k * 68 + tx * 4]);
            u64 wb[4] = {bcast2(w4.x), bcast2(w4.y), bcast2(w4.z), bcast2(w4.w)};
#pragma unroll
            for (int j = 0; j < 4; j++) {
                fma2(acc[0][j], a0, wb[j], acc[0][j]);
                fma2(acc[1][j], a1, wb[j], acc[1][j]);
            }
        }
        float* ob = out + (size_t)b * CC * HWSZ + (size_t)row * WW + x0;
#pragma unroll
        for (int j = 0; j < 4; j++) {
            float2 u0 = unpk(acc[0][j]), u1 = unpk(acc[1][j]);
            float4 o = {u0.x, u0.y, u1.x, u1.y};
            int co = tx * 4 + j;
            *reinterpret_cast<float4*>(ob + (size_t)co * HWSZ + ty * 4) = o;
        }
    }
}

// ---------------------------------------------------------------------------
extern "C" void kernel_launch(void* const* d_in, const int* in_sizes, int n_in,
                              void* d_out, int out_size) {
    const float* inp = (const float*)d_in[0];
    const float* Wv  = (const float*)d_in[1];
    const float* bv  = (const float*)d_in[2];
    const float* Wdw = (const float*)d_in[3];
    const float* bdw = (const float*)d_in[4];
    const float* Wom = (const float*)d_in[5];
    const float* bom = (const float*)d_in[6];
    const float* Wo  = (const float*)d_in[7];
    float* out = (float*)d_out;

    const int VAL_SMEM  = (64 * 132 + 64 * 68) * 4;
    const int DWSO_SMEM = 13680 * 4;
    cudaFuncSetAttribute(k_value, cudaFuncAttributeMaxDynamicSharedMemorySize, VAL_SMEM);
    cudaFuncSetAttribute(k_dwso,  cudaFuncAttributeMaxDynamicSharedMemorySize, DWSO_SMEM);

    k_value<<<NPIX / 128, 256, VAL_SMEM>>>  (inp, Wv, bv);
    k_dwso <<<NBLK,       256, DWSO_SMEM>>> (inp, Wdw, bdw, Wom, bom, Wo, out);
}